// round 3
// baseline (speedup 1.0000x reference)
#include <cuda_runtime.h>
#include <cstddef>

// DCTFeatureModel — collapsed linear model:
// feat[b,s,o] = sum_{t,ij} xc[b,s,t,ij] * Veff[s,o,t,ij] + bias[s,o]
//   xc[b,s,t,ij]    = sum_c x[b, s*256 + c*32 + t, ij]
//   Veff[s,o,t,i,j] = (1/8) sum_{f,p,q} Ct[f,t] Cs[p,i] Cs[q,j] W[s,o,f,p,q]
// out[b, s*64+o] = leaky_relu(feat)

#define NSW 2
#define NF 64
#define KSPLIT 16   // t split into 16 chunks of 2
#define MTILES 16   // batch split into 16 tiles of 64

__device__ __align__(16) float g_veff[NSW * 32 * 64 * 64];        // [s][t][ij][o], 1 MB
__device__ __align__(16) float g_part[KSPLIT * 1024 * NSW * NF];  // 8 MB

typedef unsigned long long u64;

__device__ __forceinline__ u64 pk2(float a, float b) {
    u64 r; asm("mov.b64 %0,{%1,%2};" : "=l"(r) : "f"(a), "f"(b)); return r;
}
__device__ __forceinline__ float2 up2(u64 a) {
    float2 v; asm("mov.b64 {%0,%1},%2;" : "=f"(v.x), "=f"(v.y) : "l"(a)); return v;
}
__device__ __forceinline__ void fma2(u64& d, u64 a, u64 b) {
    asm("fma.rn.f32x2 %0,%1,%2,%0;" : "+l"(d) : "l"(a), "l"(b));
}
__device__ __forceinline__ u64 add2(u64 a, u64 b) {
    u64 r; asm("add.rn.f32x2 %0,%1,%2;" : "=l"(r) : "l"(a), "l"(b)); return r;
}

// ---------------------------------------------------------------------------
// prep: one CTA per (s, o, t-quarter) -> 512 CTAs (was 128, grid-starved)
// ---------------------------------------------------------------------------
__global__ void __launch_bounds__(256) prep_kernel(const float* __restrict__ W) {
    __shared__ float A[2048];    // W[s,o] full
    __shared__ float Bf[512];    // stage1 out: [tl][pq], tl<8
    __shared__ float B2[512];    // stage2 out
    __shared__ float Ct[256];    // [tl][f]  = 2 cos(pi*(2t+1)*f/64), t = tq*8+tl
    __shared__ float Cs[64];     // [i][p]   = 2 cos(pi*(2i+1)*p/16)

    const int tid = threadIdx.x;
    const int bx = blockIdx.x;        // s*256 + o*4 + tq
    const int tq = bx & 3;
    const int o = (bx >> 2) & 63;
    const int s = bx >> 8;

    {
        int tl = tid >> 5, f = tid & 31;
        int t = tq * 8 + tl;
        Ct[tid] = 2.0f * cospif((float)((2 * t + 1) * f) / 64.0f);
    }
    if (tid < 64) {
        int i = tid >> 3, p = tid & 7;
        Cs[tid] = 2.0f * cospif((float)((2 * i + 1) * p) / 16.0f);
    }
    const float* Wso = W + ((size_t)(s * 64 + o) << 11);
#pragma unroll
    for (int r = 0; r < 8; ++r) A[tid + 256 * r] = Wso[tid + 256 * r];
    __syncthreads();

    // stage 1: f -> t (only our 8 t's)
#pragma unroll
    for (int r = 0; r < 2; ++r) {
        int idx = tid + 256 * r;
        int tl = idx >> 6, pq = idx & 63;
        float acc = 0.0f;
#pragma unroll
        for (int f = 0; f < 32; ++f) acc = fmaf(Ct[tl * 32 + f], A[f * 64 + pq], acc);
        Bf[idx] = acc;
    }
    __syncthreads();

    // stage 2: p -> i
#pragma unroll
    for (int r = 0; r < 2; ++r) {
        int idx = tid + 256 * r;
        int tl = idx >> 6, i = (idx >> 3) & 7, q = idx & 7;
        float acc = 0.0f;
#pragma unroll
        for (int p = 0; p < 8; ++p) acc = fmaf(Cs[i * 8 + p], Bf[tl * 64 + p * 8 + q], acc);
        B2[idx] = acc;
    }
    __syncthreads();

    // stage 3: q -> j, scale 1/8
#pragma unroll
    for (int r = 0; r < 2; ++r) {
        int idx = tid + 256 * r;
        int tl = idx >> 6, i = (idx >> 3) & 7, j = idx & 7;
        float acc = 0.0f;
#pragma unroll
        for (int q = 0; q < 8; ++q) acc = fmaf(Cs[j * 8 + q], B2[tl * 64 + i * 8 + q], acc);
        int t = tq * 8 + tl;
        g_veff[(((s * 32 + t) << 6) + (i * 8 + j)) * 64 + o] = 0.125f * acc;
    }
}

// ---------------------------------------------------------------------------
// main: grid = 512 CTAs, 256 threads, occ 4 (single wave).
// CTA: 64 b x 64 o, K = 128 (4 phases of 32 k), c-reduction fused into load,
// double-buffered smem, two staged LDG groups in flight for latency hiding.
// ---------------------------------------------------------------------------
__global__ void __launch_bounds__(256, 4) main_kernel(const float* __restrict__ x) {
    __shared__ __align__(16) float xs[2][32][68];  // [buf][ij][b]
    __shared__ __align__(16) float ws[2][32][64];  // [buf][ij][o]

    const int tid = threadIdx.x;
    const int bx = blockIdx.x;
    const int ks = bx & 15;
    const int mt = (bx >> 4) & 15;
    const int s = bx >> 8;

    const int ijp = tid & 15, bb = tid >> 4;  // load map
    const int tx = tid & 15, ty = tid >> 4;   // compute map

    // ks and s folded into bases; per-phase offsets are compile-time constants.
    const float* xb = x + (size_t)(mt * 64 + bb * 4) * 32768 + (size_t)s * 16384
                        + (size_t)ks * 128 + 2 * ijp;
    const float4* wb = (const float4*)(g_veff + ((size_t)s * 32 + ks * 2) * 4096) + tid;

    u64 acc[8] = {};          // [i*4+j]: b = 4ty+2i+{0,1}, o = 4tx+j
    u64 xr0[8], xr1[8];

#define XOFF(ph) ((((ph) >> 1) * 64) + (((ph) & 1) * 32))
#define WOFF(ph) ((((ph) >> 1) * 1024) + (((ph) & 1) * 512))

#define LDG_U(ph, u, R)                                                       \
    do {                                                                      \
        const u64* p = (const u64*)(xb + (size_t)(u) * 32768 + XOFF(ph));     \
        _Pragma("unroll") for (int c = 0; c < 8; ++c) R[c] = p[c * 1024];     \
    } while (0)

#define STS_U(buf, u, R)                                                      \
    do {                                                                      \
        u64 s0 = add2(add2(R[0], R[1]), add2(R[2], R[3]));                    \
        u64 s1 = add2(add2(R[4], R[5]), add2(R[6], R[7]));                    \
        float2 v = up2(add2(s0, s1));                                         \
        xs[buf][2 * ijp][bb * 4 + (u)] = v.x;                                 \
        xs[buf][2 * ijp + 1][bb * 4 + (u)] = v.y;                             \
    } while (0)

#define COMP8(buf, k0)                                                        \
    do {                                                                      \
        _Pragma("unroll") for (int k = (k0); k < (k0) + 8; ++k) {             \
            ulonglong2 xp = *(const ulonglong2*)&xs[buf][k][4 * ty];          \
            float4 wv = *(const float4*)&ws[buf][k][4 * tx];                  \
            u64 w0 = pk2(wv.x, wv.x), w1 = pk2(wv.y, wv.y);                   \
            u64 w2 = pk2(wv.z, wv.z), w3 = pk2(wv.w, wv.w);                   \
            fma2(acc[0], xp.x, w0); fma2(acc[4], xp.y, w0);                   \
            fma2(acc[1], xp.x, w1); fma2(acc[5], xp.y, w1);                   \
            fma2(acc[2], xp.x, w2); fma2(acc[6], xp.y, w2);                   \
            fma2(acc[3], xp.x, w3); fma2(acc[7], xp.y, w3);                   \
        }                                                                     \
    } while (0)

    // prologue: fill buffer 0 with phase 0
    {
        float4 w0 = wb[WOFF(0)];
        float4 w1 = wb[WOFF(0) + 256];
        LDG_U(0, 0, xr0); LDG_U(0, 1, xr1);
        STS_U(0, 0, xr0); STS_U(0, 1, xr1);
        LDG_U(0, 2, xr0); LDG_U(0, 3, xr1);
        STS_U(0, 2, xr0); STS_U(0, 3, xr1);
        ((float4*)&ws[0][0][0])[tid] = w0;
        ((float4*)&ws[0][0][0])[tid + 256] = w1;
    }
    __syncthreads();

#pragma unroll
    for (int ph = 0; ph < 4; ++ph) {
        const int buf = ph & 1, nb = buf ^ 1;
        if (ph < 3) {
            // first half: issue 2 LDG groups + w0, compute 16 k, then store
            float4 w0 = wb[WOFF(ph + 1)];
            LDG_U(ph + 1, 0, xr0);
            LDG_U(ph + 1, 1, xr1);
            COMP8(buf, 0); COMP8(buf, 8);
            ((float4*)&ws[nb][0][0])[tid] = w0;
            STS_U(nb, 0, xr0); STS_U(nb, 1, xr1);
            // second half
            float4 w1 = wb[WOFF(ph + 1) + 256];
            LDG_U(ph + 1, 2, xr0);
            LDG_U(ph + 1, 3, xr1);
            COMP8(buf, 16); COMP8(buf, 24);
            ((float4*)&ws[nb][0][0])[tid + 256] = w1;
            STS_U(nb, 2, xr0); STS_U(nb, 3, xr1);
        } else {
            COMP8(buf, 0); COMP8(buf, 8); COMP8(buf, 16); COMP8(buf, 24);
        }
        __syncthreads();
    }

    // write partials: g_part[ks][b][s*64+o]
    const int b0 = mt * 64 + 4 * ty;
    const int obase = s * 64 + 4 * tx;
#pragma unroll
    for (int p = 0; p < 2; ++p) {
        float2 c0 = up2(acc[p * 4 + 0]), c1 = up2(acc[p * 4 + 1]);
        float2 c2 = up2(acc[p * 4 + 2]), c3 = up2(acc[p * 4 + 3]);
        float4 r0 = make_float4(c0.x, c1.x, c2.x, c3.x);
        float4 r1 = make_float4(c0.y, c1.y, c2.y, c3.y);
        *(float4*)(g_part + ((size_t)ks << 17) + (size_t)(b0 + 2 * p) * 128 + obase) = r0;
        *(float4*)(g_part + ((size_t)ks << 17) + (size_t)(b0 + 2 * p + 1) * 128 + obase) = r1;
    }
}

// ---------------------------------------------------------------------------
// epilogue: sum KSPLIT partials + bias, LeakyReLU  (float4 / packed)
// ---------------------------------------------------------------------------
__global__ void __launch_bounds__(256) epi_kernel(const float* __restrict__ bias,
                                                  float* __restrict__ out) {
    const int i4 = (blockIdx.x * 256 + threadIdx.x) * 4;  // grid 128 -> 131072 elems
    float4 bv = *(const float4*)(bias + (i4 & 127));
    u64 a0 = pk2(bv.x, bv.y), a1 = pk2(bv.z, bv.w);
#pragma unroll
    for (int k = 0; k < KSPLIT; ++k) {
        ulonglong2 p = *(const ulonglong2*)(g_part + ((size_t)k << 17) + i4);
        a0 = add2(a0, p.x);
        a1 = add2(a1, p.y);
    }
    float2 f0 = up2(a0), f1 = up2(a1);
    float4 r;
    r.x = (f0.x >= 0.0f) ? f0.x : 0.02f * f0.x;
    r.y = (f0.y >= 0.0f) ? f0.y : 0.02f * f0.y;
    r.z = (f1.x >= 0.0f) ? f1.x : 0.02f * f1.x;
    r.w = (f1.y >= 0.0f) ? f1.y : 0.02f * f1.y;
    *(float4*)(out + i4) = r;
}

// ---------------------------------------------------------------------------
extern "C" void kernel_launch(void* const* d_in, const int* in_sizes, int n_in,
                              void* d_out, int out_size) {
    const float* x = nullptr;
    const float* W = nullptr;
    const float* bias = nullptr;
    for (int i = 0; i < n_in; ++i) {
        if (in_sizes[i] == 1024 * 512 * 64) x = (const float*)d_in[i];
        else if (in_sizes[i] == NSW * NF * 32 * 64) W = (const float*)d_in[i];
        else if (in_sizes[i] == NSW * NF) bias = (const float*)d_in[i];
    }
    if (!x) x = (const float*)d_in[0];
    if (!W) W = (const float*)d_in[1];
    if (!bias) bias = (const float*)d_in[2];

    prep_kernel<<<NSW * NF * 4, 256>>>(W);
    main_kernel<<<NSW * MTILES * KSPLIT, 256>>>(x);
    epi_kernel<<<(1024 * NSW * NF) / (256 * 4), 256>>>(bias, (float*)d_out);
}

// round 4
// speedup vs baseline: 1.4687x; 1.4687x over previous
#include <cuda_runtime.h>
#include <cstddef>

// DCTFeatureModel — collapsed linear model:
// feat[b,s,o] = sum_{t,ij} xc[b,s,t,ij] * Veff[s,o,t,ij] + bias[s,o]
//   xc[b,s,t,ij]    = sum_c x[b, s*256 + c*32 + t, ij]
//   Veff[s,o,t,i,j] = (1/8) sum_{f,p,q} Ct[f,t] Cs[p,i] Cs[q,j] W[s,o,f,p,q]
// out[b, s*64+o] = leaky_relu(feat)

#define NSW 2
#define NF 64
#define KSPLIT 16   // t split into 16 chunks of 2
#define MTILES 16   // batch split into 16 tiles of 64

__device__ __align__(16) float g_veff[NSW * 32 * 64 * 64];        // [s][t][ij][o], 1 MB
__device__ __align__(16) float g_part[KSPLIT * 1024 * NSW * NF];  // 8 MB

typedef unsigned long long u64;

__device__ __forceinline__ u64 pk2(float a, float b) {
    u64 r; asm("mov.b64 %0,{%1,%2};" : "=l"(r) : "f"(a), "f"(b)); return r;
}
__device__ __forceinline__ float2 up2(u64 a) {
    float2 v; asm("mov.b64 {%0,%1},%2;" : "=f"(v.x), "=f"(v.y) : "l"(a)); return v;
}
__device__ __forceinline__ void fma2(u64& d, u64 a, u64 b) {
    asm("fma.rn.f32x2 %0,%1,%2,%0;" : "+l"(d) : "l"(a), "l"(b));
}
__device__ __forceinline__ u64 add2(u64 a, u64 b) {
    u64 r; asm("add.rn.f32x2 %0,%1,%2;" : "=l"(r) : "l"(a), "l"(b)); return r;
}

// ---------------------------------------------------------------------------
// prep: one CTA per (s,o), 128 CTAs. LDS-bound before; now register-blocked
// 2t x 4-element tiles with LDS.128 everywhere (~5x fewer LDS instructions).
// ---------------------------------------------------------------------------
__global__ void __launch_bounds__(256) prep_kernel(const float* __restrict__ W) {
    __shared__ __align__(16) float A[2048];    // W[s,o][f][pq]
    __shared__ __align__(16) float Bf[2048];   // [t][p*8+q]
    __shared__ __align__(16) float B2[2048];   // [t][i*8+q]
    __shared__ __align__(16) float Ct[1024];   // [t][f] = 2 cos(pi(2t+1)f/64)
    __shared__ __align__(16) float Cs[64];     // [i][p] = 2 cos(pi(2i+1)p/16)
    __shared__ __align__(16) float Cst[64];    // [q][j] = Cs[j][q] (transposed)

    const int tid = threadIdx.x;
    const int s = blockIdx.x >> 6;
    const int o = blockIdx.x & 63;

    // ---- tables ----
#pragma unroll
    for (int r = 0; r < 4; ++r) {
        int idx = tid + 256 * r;
        int t = idx >> 5, f = idx & 31;
        Ct[idx] = 2.0f * cospif((float)((2 * t + 1) * f) / 64.0f);
    }
    if (tid < 64) {
        int i = tid >> 3, p = tid & 7;
        Cs[tid] = 2.0f * cospif((float)((2 * i + 1) * p) / 16.0f);
    } else if (tid < 128) {
        int idx = tid - 64;
        int q = idx >> 3, j = idx & 7;
        Cst[idx] = 2.0f * cospif((float)((2 * j + 1) * q) / 16.0f);
    }
    // ---- W tile load (float4) ----
    {
        const float4* Wso = (const float4*)(W + ((size_t)(s * 64 + o) << 11));
        ((float4*)A)[tid] = Wso[tid];
        ((float4*)A)[tid + 256] = Wso[tid + 256];
    }
    __syncthreads();

    const int a = tid >> 4;          // t pair: t0 = 2a, t1 = 2a+1
    const int t0 = 2 * a, t1 = 2 * a + 1;
    const int g16 = tid & 15;

    // ---- stage 1: f -> t.  thread tile: 2t x 4pq (pq = 4*g16) ----
    {
        u64 ac00 = 0, ac01 = 0, ac10 = 0, ac11 = 0;
#pragma unroll
        for (int f = 0; f < 32; ++f) {
            float4 av = ((const float4*)A)[f * 16 + g16];
            u64 a01 = pk2(av.x, av.y), a23 = pk2(av.z, av.w);
            u64 w0 = pk2(Ct[t0 * 32 + f], Ct[t0 * 32 + f]);
            u64 w1 = pk2(Ct[t1 * 32 + f], Ct[t1 * 32 + f]);
            fma2(ac00, a01, w0); fma2(ac01, a23, w0);
            fma2(ac10, a01, w1); fma2(ac11, a23, w1);
        }
        float2 v0 = up2(ac00), v1 = up2(ac01), v2 = up2(ac10), v3 = up2(ac11);
        *(float4*)&Bf[t0 * 64 + 4 * g16] = make_float4(v0.x, v0.y, v1.x, v1.y);
        *(float4*)&Bf[t1 * 64 + 4 * g16] = make_float4(v2.x, v2.y, v3.x, v3.y);
    }
    __syncthreads();

    // ---- stage 2: p -> i.  thread tile: 2t x (i fixed) x 4q ----
    const int i8 = (tid >> 1) & 7;   // i
    const int qg = tid & 1;          // q half: q0 = 4*qg
    {
        u64 ac00 = 0, ac01 = 0, ac10 = 0, ac11 = 0;
#pragma unroll
        for (int p = 0; p < 8; ++p) {
            float cs = Cs[i8 * 8 + p];
            u64 w = pk2(cs, cs);
            float4 b0 = *(const float4*)&Bf[t0 * 64 + p * 8 + 4 * qg];
            float4 b1 = *(const float4*)&Bf[t1 * 64 + p * 8 + 4 * qg];
            fma2(ac00, pk2(b0.x, b0.y), w); fma2(ac01, pk2(b0.z, b0.w), w);
            fma2(ac10, pk2(b1.x, b1.y), w); fma2(ac11, pk2(b1.z, b1.w), w);
        }
        float2 v0 = up2(ac00), v1 = up2(ac01), v2 = up2(ac10), v3 = up2(ac11);
        *(float4*)&B2[t0 * 64 + i8 * 8 + 4 * qg] = make_float4(v0.x, v0.y, v1.x, v1.y);
        *(float4*)&B2[t1 * 64 + i8 * 8 + 4 * qg] = make_float4(v2.x, v2.y, v3.x, v3.y);
    }
    __syncthreads();

    // ---- stage 3: q -> j.  thread tile: 2t x (i fixed) x 4j (j0 = 4*jg) ----
    {
        const int jg = qg;
        float4 r0a = *(const float4*)&B2[t0 * 64 + i8 * 8];
        float4 r0b = *(const float4*)&B2[t0 * 64 + i8 * 8 + 4];
        float4 r1a = *(const float4*)&B2[t1 * 64 + i8 * 8];
        float4 r1b = *(const float4*)&B2[t1 * 64 + i8 * 8 + 4];
        float b0q[8] = {r0a.x, r0a.y, r0a.z, r0a.w, r0b.x, r0b.y, r0b.z, r0b.w};
        float b1q[8] = {r1a.x, r1a.y, r1a.z, r1a.w, r1b.x, r1b.y, r1b.z, r1b.w};
        u64 ac[4] = {};  // ac[j] packs (t0, t1)
#pragma unroll
        for (int q = 0; q < 8; ++q) {
            float4 cj = *(const float4*)&Cst[q * 8 + 4 * jg];
            u64 bp = pk2(b0q[q], b1q[q]);
            fma2(ac[0], bp, pk2(cj.x, cj.x));
            fma2(ac[1], bp, pk2(cj.y, cj.y));
            fma2(ac[2], bp, pk2(cj.z, cj.z));
            fma2(ac[3], bp, pk2(cj.w, cj.w));
        }
        // write g_veff[s][t][i*8+j][o]
        float* base0 = g_veff + (((size_t)(s * 32 + t0) << 6) + i8 * 8 + 4 * jg) * 64 + o;
        float* base1 = g_veff + (((size_t)(s * 32 + t1) << 6) + i8 * 8 + 4 * jg) * 64 + o;
#pragma unroll
        for (int j = 0; j < 4; ++j) {
            float2 v = up2(ac[j]);
            base0[j * 64] = 0.125f * v.x;
            base1[j * 64] = 0.125f * v.y;
        }
    }
}

// ---------------------------------------------------------------------------
// main: grid = 512 CTAs, 256 threads, occ 4 (single wave). ROUND-2 VERSION
// (reverted: dual staged LDG groups in round 3 caused reg pressure/spills).
// ---------------------------------------------------------------------------
__global__ void __launch_bounds__(256, 4) main_kernel(const float* __restrict__ x) {
    __shared__ __align__(16) float xs[2][32][68];  // [buf][ij][b]
    __shared__ __align__(16) float ws[2][32][64];  // [buf][ij][o]

    const int tid = threadIdx.x;
    const int bx = blockIdx.x;
    const int ks = bx & 15;
    const int mt = (bx >> 4) & 15;
    const int s = bx >> 8;

    const int ijp = tid & 15, bb = tid >> 4;  // load map
    const int tx = tid & 15, ty = tid >> 4;   // compute map

    const float* xb = x + (size_t)(mt * 64 + bb * 4) * 32768 + (size_t)s * 16384 + 2 * ijp;

    u64 acc[2][4] = {};
    u64 xr[8];
    float4 wr0, wr1;

#define PH_T(ph) (ks * 2 + ((ph) >> 1))
#define PH_OFF(ph) ((size_t)(PH_T(ph)) * 64 + ((ph) & 1) * 32)

#define LDG_U(ph, u)                                                          \
    do {                                                                      \
        const u64* p = (const u64*)(xb + (size_t)(u) * 32768 + PH_OFF(ph));   \
        _Pragma("unroll") for (int c = 0; c < 8; ++c) xr[c] = p[c * 1024];    \
    } while (0)

#define STS_U(buf, u)                                                         \
    do {                                                                      \
        u64 s0 = add2(add2(xr[0], xr[1]), add2(xr[2], xr[3]));                \
        u64 s1 = add2(add2(xr[4], xr[5]), add2(xr[6], xr[7]));                \
        float2 v = up2(add2(s0, s1));                                         \
        xs[buf][2 * ijp][bb * 4 + (u)] = v.x;                                 \
        xs[buf][2 * ijp + 1][bb * 4 + (u)] = v.y;                             \
    } while (0)

#define LDG_W(ph)                                                             \
    do {                                                                      \
        const float4* wp = (const float4*)(g_veff +                          \
            (((size_t)s * 32 + PH_T(ph)) * 64 + ((ph) & 1) * 32) * 64);       \
        wr0 = wp[tid]; wr1 = wp[tid + 256];                                   \
    } while (0)

#define STS_W(buf)                                                            \
    do {                                                                      \
        float4* wd = (float4*)&ws[buf][0][0];                                 \
        wd[tid] = wr0; wd[tid + 256] = wr1;                                   \
    } while (0)

#define COMP8(buf, k0)                                                        \
    do {                                                                      \
        _Pragma("unroll") for (int k = (k0); k < (k0) + 8; ++k) {             \
            ulonglong2 xp = *(const ulonglong2*)&xs[buf][k][4 * ty];          \
            float4 wv = *(const float4*)&ws[buf][k][4 * tx];                  \
            u64 w0 = pk2(wv.x, wv.x), w1 = pk2(wv.y, wv.y);                   \
            u64 w2 = pk2(wv.z, wv.z), w3 = pk2(wv.w, wv.w);                   \
            fma2(acc[0][0], xp.x, w0); fma2(acc[1][0], xp.y, w0);             \
            fma2(acc[0][1], xp.x, w1); fma2(acc[1][1], xp.y, w1);             \
            fma2(acc[0][2], xp.x, w2); fma2(acc[1][2], xp.y, w2);             \
            fma2(acc[0][3], xp.x, w3); fma2(acc[1][3], xp.y, w3);             \
        }                                                                     \
    } while (0)

    // prologue: fill buffer 0 with phase 0
    LDG_W(0);
    LDG_U(0, 0); STS_U(0, 0);
    LDG_U(0, 1); STS_U(0, 1);
    LDG_U(0, 2); STS_U(0, 2);
    LDG_U(0, 3); STS_U(0, 3);
    STS_W(0);
    __syncthreads();

#pragma unroll
    for (int ph = 0; ph < 4; ++ph) {
        const int buf = ph & 1, nb = buf ^ 1;
        if (ph < 3) {
            LDG_W(ph + 1);
            LDG_U(ph + 1, 0); COMP8(buf, 0);  STS_U(nb, 0);
            LDG_U(ph + 1, 1); COMP8(buf, 8);  STS_U(nb, 1);
            LDG_U(ph + 1, 2); COMP8(buf, 16); STS_U(nb, 2);
            LDG_U(ph + 1, 3); COMP8(buf, 24); STS_U(nb, 3);
            STS_W(nb);
        } else {
            COMP8(buf, 0); COMP8(buf, 8); COMP8(buf, 16); COMP8(buf, 24);
        }
        __syncthreads();
    }

    // write partials: g_part[ks][b][s*64+o]
    const int b0 = mt * 64 + 4 * ty;
    const int obase = s * 64 + 4 * tx;
#pragma unroll
    for (int p = 0; p < 2; ++p) {
        float2 c0 = up2(acc[p][0]), c1 = up2(acc[p][1]);
        float2 c2 = up2(acc[p][2]), c3 = up2(acc[p][3]);
        float4 r0 = make_float4(c0.x, c1.x, c2.x, c3.x);
        float4 r1 = make_float4(c0.y, c1.y, c2.y, c3.y);
        *(float4*)(g_part + ((size_t)ks << 17) + (size_t)(b0 + 2 * p) * 128 + obase) = r0;
        *(float4*)(g_part + ((size_t)ks << 17) + (size_t)(b0 + 2 * p + 1) * 128 + obase) = r1;
    }
}

// ---------------------------------------------------------------------------
// epilogue: sum KSPLIT partials + bias, LeakyReLU  (float4 / packed)
// ---------------------------------------------------------------------------
__global__ void __launch_bounds__(256) epi_kernel(const float* __restrict__ bias,
                                                  float* __restrict__ out) {
    const int i4 = (blockIdx.x * 256 + threadIdx.x) * 4;  // grid 128 -> 131072 elems
    float4 bv = *(const float4*)(bias + (i4 & 127));
    u64 a0 = pk2(bv.x, bv.y), a1 = pk2(bv.z, bv.w);
#pragma unroll
    for (int k = 0; k < KSPLIT; ++k) {
        ulonglong2 p = *(const ulonglong2*)(g_part + ((size_t)k << 17) + i4);
        a0 = add2(a0, p.x);
        a1 = add2(a1, p.y);
    }
    float2 f0 = up2(a0), f1 = up2(a1);
    float4 r;
    r.x = (f0.x >= 0.0f) ? f0.x : 0.02f * f0.x;
    r.y = (f0.y >= 0.0f) ? f0.y : 0.02f * f0.y;
    r.z = (f1.x >= 0.0f) ? f1.x : 0.02f * f1.x;
    r.w = (f1.y >= 0.0f) ? f1.y : 0.02f * f1.y;
    *(float4*)(out + i4) = r;
}

// ---------------------------------------------------------------------------
extern "C" void kernel_launch(void* const* d_in, const int* in_sizes, int n_in,
                              void* d_out, int out_size) {
    const float* x = nullptr;
    const float* W = nullptr;
    const float* bias = nullptr;
    for (int i = 0; i < n_in; ++i) {
        if (in_sizes[i] == 1024 * 512 * 64) x = (const float*)d_in[i];
        else if (in_sizes[i] == NSW * NF * 32 * 64) W = (const float*)d_in[i];
        else if (in_sizes[i] == NSW * NF) bias = (const float*)d_in[i];
    }
    if (!x) x = (const float*)d_in[0];
    if (!W) W = (const float*)d_in[1];
    if (!bias) bias = (const float*)d_in[2];

    prep_kernel<<<NSW * NF, 256>>>(W);
    main_kernel<<<NSW * MTILES * KSPLIT, 256>>>(x);
    epi_kernel<<<(1024 * NSW * NF) / (256 * 4), 256>>>(bias, (float*)d_out);
}